// round 8
// baseline (speedup 1.0000x reference)
#include <cuda_runtime.h>
#include <cuda_bf16.h>
#include <cstdint>

#define S 2048
#define H 1024
#define E 8
#define INTER 2048
#define TWO_I 4096
#define ALPHA 1.702f
#define LIMIT 7.0f

// ---------------- device scratch (device-code references ONLY) ----------------
__device__ int   g_cnt[E];
__device__ int   g_tok[E * S];
__device__ float g_wt[E * S];
// x quantized: per-token-row scale, 2 int8 digits
__device__ __align__(128) char  g_x8h[S * H];
__device__ __align__(128) char  g_x8l[S * H];
__device__ float g_xs[S];
// gate_up weights transposed+quantized: [E][N=4096][K=1024] int8 h/l + per-N-row scale
__device__ __align__(128) char  g_gu8h[(size_t)E * TWO_I * H];
__device__ __align__(128) char  g_gu8l[(size_t)E * TWO_I * H];
__device__ float g_gus[E * TWO_I];
__device__ float g_guinv[E * TWO_I];
// down weights transposed+quantized: [E][N=H][K=INTER]
__device__ __align__(128) char  g_dw8h[(size_t)E * H * INTER];
__device__ __align__(128) char  g_dw8l[(size_t)E * H * INTER];
__device__ float g_dws[E * H];
__device__ float g_dwinv[E * H];
// activations: fp32 from gate_up epilogue, then quantized
__device__ __align__(128) float g_actf[(size_t)E * S * INTER];
__device__ __align__(128) char  g_a8h[(size_t)E * S * INTER];
__device__ __align__(128) char  g_a8l[(size_t)E * S * INTER];
__device__ float g_as[E * S];

// ---------------- helpers ----------------
__device__ __forceinline__ uint32_t s2u(const void* p) {
    uint32_t a;
    asm("{ .reg .u64 t; cvta.to.shared.u64 t, %1; cvt.u32.u64 %0, t; }" : "=r"(a) : "l"(p));
    return a;
}
__device__ __forceinline__ uint32_t swz128(uint32_t o) { return o ^ ((o >> 3) & 0x70); }

#define CP16(dst, src) \
    asm volatile("cp.async.cg.shared.global [%0], [%1], 16;" :: "r"(dst), "l"(src) : "memory")
#define CP_COMMIT() asm volatile("cp.async.commit_group;" ::: "memory")
#define CP_WAIT0()  asm volatile("cp.async.wait_group 0;" ::: "memory")

__device__ __forceinline__ void ldsm4(uint32_t addr, uint32_t* r) {
    asm volatile("ldmatrix.sync.aligned.m8n8.x4.shared.b16 {%0,%1,%2,%3}, [%4];"
                 : "=r"(r[0]), "=r"(r[1]), "=r"(r[2]), "=r"(r[3]) : "r"(addr));
}
__device__ __forceinline__ void imma(int* d, const uint32_t* a, uint32_t b0, uint32_t b1) {
    asm volatile(
        "mma.sync.aligned.m16n8k32.row.col.s32.s8.s8.s32 "
        "{%0,%1,%2,%3}, {%4,%5,%6,%7}, {%8,%9}, {%0,%1,%2,%3};"
        : "+r"(d[0]), "+r"(d[1]), "+r"(d[2]), "+r"(d[3])
        : "r"(a[0]), "r"(a[1]), "r"(a[2]), "r"(a[3]), "r"(b0), "r"(b1));
}
// quantize val*inv -> (h, l) with val ~ s*(h + l/128)
__device__ __forceinline__ void quant2(float t, int& h, int& l) {
    float hf = rintf(t);
    h = (int)hf;
    l = (int)rintf((t - hf) * 128.0f);
}

// Stage: Ah 16K | Al 16K | Bh 8K | Bl 8K = 48KB (K-chunk = 128 int8 bytes)
#define AOFF_L 16384
#define BOFF_H 32768
#define BOFF_L 40960
#define STAGE  49152
#define SMEM_REQ (1024 + 2 * STAGE)

// one K=128 chunk; block tile 128x64, warp tile 64x32 (4 warps); 4 ksteps of K32
__device__ __forceinline__ void compute_chunk(uint32_t base, int wm, int wn, int lane,
                                              int acc1[4][4][4], int acc2[4][4][4])
{
    uint32_t sAh = base, sAl = base + AOFF_L, sBh = base + BOFF_H, sBl = base + BOFF_L;
    int arow = wm + (lane & 15);
    int brow = wn + (lane & 15);
    uint32_t klane = (uint32_t)((lane >> 4) << 4);
#pragma unroll
    for (int ks = 0; ks < 4; ks++) {
        uint32_t kb = (uint32_t)(ks * 32) + klane;
        uint32_t ah[4][4], al[4][4];
#pragma unroll
        for (int mf = 0; mf < 4; mf++) {
            uint32_t off = swz128((uint32_t)((arow + mf * 16) * 128) + kb);
            ldsm4(sAh + off, ah[mf]);
            ldsm4(sAl + off, al[mf]);
        }
#pragma unroll
        for (int nh = 0; nh < 2; nh++) {
            uint32_t boff = swz128((uint32_t)((brow + nh * 16) * 128) + kb);
            uint32_t bh[4], bl[4];
            ldsm4(sBh + boff, bh);
            ldsm4(sBl + boff, bl);
#pragma unroll
            for (int mf = 0; mf < 4; mf++) {
                imma(acc1[mf][2 * nh],     ah[mf], bh[0], bh[2]);
                imma(acc2[mf][2 * nh],     ah[mf], bl[0], bl[2]);
                imma(acc2[mf][2 * nh],     al[mf], bh[0], bh[2]);
                imma(acc1[mf][2 * nh + 1], ah[mf], bh[1], bh[3]);
                imma(acc2[mf][2 * nh + 1], ah[mf], bl[1], bl[3]);
                imma(acc2[mf][2 * nh + 1], al[mf], bh[1], bh[3]);
            }
        }
    }
}

// 128 threads: A rows 0..127 (8 CP16 per array), B rows 0..63 (4 per array).
// Offsets are in BYTES (int8 data).
__device__ __forceinline__ void issue_chunk(
    uint32_t base, int k0,
    const char* Ah, const char* Al, const char* Bh, const char* Bl,
    const size_t* asrc, const size_t* bsrc,
    const uint32_t* adst, const uint32_t* bdst)
{
#pragma unroll
    for (int i = 0; i < 8; i++) {
        CP16(base +          adst[i], Ah + asrc[i] + k0);
        CP16(base + AOFF_L + adst[i], Al + asrc[i] + k0);
    }
#pragma unroll
    for (int i = 0; i < 4; i++) {
        CP16(base + BOFF_H + bdst[i], Bh + bsrc[i] + k0);
        CP16(base + BOFF_L + bdst[i], Bl + bsrc[i] + k0);
    }
    CP_COMMIT();
}

// ---------------------------------------------------------------------------
__global__ void init_kernel() {
    if (threadIdx.x < E) g_cnt[threadIdx.x] = 0;
}

// ---------------------------------------------------------------------------
__global__ __launch_bounds__(256) void router_kernel(
    const float* __restrict__ x, const float* __restrict__ rw, const float* __restrict__ rb)
{
    int t = blockIdx.x;
    int tid = threadIdx.x;
    const float* xr = x + (size_t)t * H;

    float acc[E];
#pragma unroll
    for (int e = 0; e < E; e++) acc[e] = 0.0f;
    for (int h = tid; h < H; h += 256) {
        float xv = xr[h];
        const float4* wrow = (const float4*)(rw + (size_t)h * E);
        float4 w0 = wrow[0], w1 = wrow[1];
        acc[0] += xv * w0.x; acc[1] += xv * w0.y; acc[2] += xv * w0.z; acc[3] += xv * w0.w;
        acc[4] += xv * w1.x; acc[5] += xv * w1.y; acc[6] += xv * w1.z; acc[7] += xv * w1.w;
    }
    __shared__ float sm[256 * E];
#pragma unroll
    for (int e = 0; e < E; e++) sm[tid * E + e] = acc[e];
    __syncthreads();
    for (int s = 128; s > 0; s >>= 1) {
        if (tid < s) {
#pragma unroll
            for (int e = 0; e < E; e++) sm[tid * E + e] += sm[(tid + s) * E + e];
        }
        __syncthreads();
    }
    if (tid == 0) {
        float v[E];
#pragma unroll
        for (int e = 0; e < E; e++) v[e] = sm[e] + rb[e];
        int i0 = 0;
#pragma unroll
        for (int e = 1; e < E; e++) if (v[e] > v[i0]) i0 = e;
        int i1 = -1;
#pragma unroll
        for (int e = 0; e < E; e++) {
            if (e == i0) continue;
            if (i1 < 0 || v[e] > v[i1]) i1 = e;
        }
        float e1 = expf(v[i1] - v[i0]);
        float den = 1.0f + e1;
        int p0 = atomicAdd(&g_cnt[i0], 1);
        g_tok[i0 * S + p0] = t; g_wt[i0 * S + p0] = 1.0f / den;
        int p1 = atomicAdd(&g_cnt[i1], 1);
        g_tok[i1 * S + p1] = t; g_wt[i1 * S + p1] = e1 / den;
    }
}

// ---------------------------------------------------------------------------
// x -> int8 h/l with per-token-row scale. One block (256 thr) per token.
// ---------------------------------------------------------------------------
__global__ __launch_bounds__(256) void quant_x_kernel(const float* __restrict__ x) {
    int t = blockIdx.x, tid = threadIdx.x;
    const float4* xr = (const float4*)(x + (size_t)t * H);
    float4 v = xr[tid];
    float m = fmaxf(fmaxf(fabsf(v.x), fabsf(v.y)), fmaxf(fabsf(v.z), fabsf(v.w)));
    __shared__ float sm[256];
    sm[tid] = m;
    __syncthreads();
    for (int s = 128; s > 0; s >>= 1) {
        if (tid < s) sm[tid] = fmaxf(sm[tid], sm[tid + s]);
        __syncthreads();
    }
    float amax = sm[0];
    float inv = amax > 0.0f ? 127.0f / amax : 0.0f;
    if (tid == 0) g_xs[t] = amax / 127.0f;
    int h0, l0, h1, l1, h2, l2, h3, l3;
    quant2(v.x * inv, h0, l0); quant2(v.y * inv, h1, l1);
    quant2(v.z * inv, h2, l2); quant2(v.w * inv, h3, l3);
    uint32_t hp = (h0 & 0xFF) | ((h1 & 0xFF) << 8) | ((h2 & 0xFF) << 16) | ((h3 & 0xFF) << 24);
    uint32_t lp = (l0 & 0xFF) | ((l1 & 0xFF) << 8) | ((l2 & 0xFF) << 16) | ((l3 & 0xFF) << 24);
    ((uint32_t*)g_x8h)[t * 256 + tid] = hp;
    ((uint32_t*)g_x8l)[t * 256 + tid] = lp;
}

// ---------------------------------------------------------------------------
// per-output-row absmax over ORIGINAL weight layout [E][R][C] (absmax over R
// for each column c). Block: 32 cols x 8 row-partitions.
// ---------------------------------------------------------------------------
template <int WHICH>   // 0 = gate_up (R=H, C=2I), 1 = down (R=INTER, C=H)
__global__ __launch_bounds__(256) void absmax_w_kernel(const float* __restrict__ in) {
    const int R = (WHICH == 0) ? H : INTER;
    const int C = (WHICH == 0) ? TWO_I : H;
    float* gs  = (WHICH == 0) ? g_gus : g_dws;
    float* giv = (WHICH == 0) ? g_guinv : g_dwinv;

    int e = blockIdx.y;
    int tx = threadIdx.x & 31, ty = threadIdx.x >> 5;     // ty = 0..7
    int c = blockIdx.x * 32 + tx;
    const float* p = in + (size_t)e * R * C + c;
    float m = 0.0f;
    for (int r = ty; r < R; r += 8)
        m = fmaxf(m, fabsf(p[(size_t)r * C]));
    __shared__ float sm[8][33];
    sm[ty][tx] = m;
    __syncthreads();
    if (ty == 0) {
#pragma unroll
        for (int i = 1; i < 8; i++) m = fmaxf(m, sm[i][tx]);
        gs[e * C + c]  = m / 127.0f;
        giv[e * C + c] = m > 0.0f ? 127.0f / m : 0.0f;
    }
}

// ---------------------------------------------------------------------------
// weight transpose + int8 quantize: in [E][R][C] fp32 -> out [E][C][R] int8 h/l
// ---------------------------------------------------------------------------
template <int WHICH>
__global__ __launch_bounds__(256) void transpose_quant_kernel(const float* __restrict__ in) {
    const int R = (WHICH == 0) ? H : INTER;
    const int C = (WHICH == 0) ? TWO_I : H;
    char* ohi = (WHICH == 0) ? g_gu8h : g_dw8h;
    char* olo = (WHICH == 0) ? g_gu8l : g_dw8l;
    const float* giv = (WHICH == 0) ? g_guinv : g_dwinv;

    int e = blockIdx.z;
    int r0 = blockIdx.x * 64;
    int c0 = blockIdx.y * 32;
    __shared__ float t[64][33];
    int tx = threadIdx.x & 31, ty = threadIdx.x >> 5;
    const float* ib = in + ((size_t)e * R + r0) * C + c0;
#pragma unroll
    for (int i = 0; i < 8; i++)
        t[ty + 8 * i][tx] = ib[(size_t)(ty + 8 * i) * C + tx];
    __syncthreads();
#pragma unroll
    for (int i = 0; i < 4; i++) {
        int c = ty + 8 * i;
        float inv = giv[e * C + c0 + c];
        float a = t[2 * tx][c], b = t[2 * tx + 1][c];
        int ha, la, hb, lb;
        quant2(a * inv, ha, la);
        quant2(b * inv, hb, lb);
        size_t o = ((size_t)e * C + c0 + c) * R + r0 + 2 * tx;
        ohi[o] = (char)ha; ohi[o + 1] = (char)hb;
        olo[o] = (char)la; olo[o + 1] = (char)lb;
    }
}

// ---------------------------------------------------------------------------
// gate_up int8 MMA: CTA = (expert, 128-token M-tile, 32-j N-tile = 64
// interleaved gate/up cols). K = 1024 bytes, 8 chunks of 128.
// ---------------------------------------------------------------------------
__global__ __launch_bounds__(128, 2) void gateup_mma_kernel(const float* __restrict__ gub) {
    int e = blockIdx.z, mt = blockIdx.x, nt = blockIdx.y;
    int cnt = g_cnt[e];
    if (mt * 128 >= cnt) return;

    extern __shared__ char smem[];
    uint32_t T0 = (s2u(smem) + 1023) & ~1023u;
    int tid = threadIdx.x, wid = tid >> 5, lane = tid & 31;
    int wm = (wid >> 1) * 64, wn = (wid & 1) * 32;
    int j0 = nt * 32;

    int seg = tid & 7;
    size_t asrc[8], bsrc[4];
    uint32_t adst[8], bdst[4];
#pragma unroll
    for (int i = 0; i < 8; i++) {
        int row = (tid >> 3) + 16 * i;                 // 0..127
        int tr = min(mt * 128 + row, cnt - 1);
        int tok = g_tok[e * S + tr];
        asrc[i] = (size_t)tok * H + seg * 16;          // bytes
        adst[i] = swz128((uint32_t)(row * 128 + seg * 16));
    }
#pragma unroll
    for (int i = 0; i < 4; i++) {
        int row = (tid >> 3) + 16 * i;                 // 0..63
        int br = (row & 1) ? (INTER + j0 + (row >> 1)) : (j0 + (row >> 1));
        bsrc[i] = ((size_t)e * TWO_I + br) * H + seg * 16;
        bdst[i] = swz128((uint32_t)(row * 128 + seg * 16));
    }

    int acc1[4][4][4], acc2[4][4][4];
#pragma unroll
    for (int a = 0; a < 4; a++)
#pragma unroll
        for (int b = 0; b < 4; b++)
#pragma unroll
            for (int c = 0; c < 4; c++) { acc1[a][b][c] = 0; acc2[a][b][c] = 0; }

    issue_chunk(T0, 0, g_x8h, g_x8l, g_gu8h, g_gu8l, asrc, bsrc, adst, bdst);
#pragma unroll 1
    for (int c = 0; c < 8; c++) {
        CP_WAIT0();
        __syncthreads();
        if (c + 1 < 8)
            issue_chunk(T0 + ((c + 1) & 1) * STAGE, (c + 1) * 128,
                        g_x8h, g_x8l, g_gu8h, g_gu8l, asrc, bsrc, adst, bdst);
        compute_chunk(T0 + (c & 1) * STAGE, wm, wn, lane, acc1, acc2);
    }

    const float* gb = gub + (size_t)e * TWO_I;
    const float* gsc = g_gus + (size_t)e * TWO_I;
#pragma unroll
    for (int mf = 0; mf < 4; mf++) {
        int r0 = wm + mf * 16 + (lane >> 2);
#pragma unroll
        for (int half = 0; half < 2; half++) {
            int mrow = mt * 128 + r0 + half * 8;
            if (mrow >= cnt) continue;
            int tok = g_tok[e * S + mrow];
            float sx = g_xs[tok];
            size_t abase = ((size_t)e * S + mrow) * INTER;
#pragma unroll
            for (int nf = 0; nf < 4; nf++) {
                int nn = wn + nf * 8 + 2 * (lane & 3);
                int j = j0 + (nn >> 1);
                float vg = (float)acc1[mf][nf][half * 2 + 0]
                         + (float)acc2[mf][nf][half * 2 + 0] * 0.0078125f;
                float vu = (float)acc1[mf][nf][half * 2 + 1]
                         + (float)acc2[mf][nf][half * 2 + 1] * 0.0078125f;
                float g = sx * gsc[j] * vg + gb[j];
                float u = sx * gsc[INTER + j] * vu + gb[INTER + j];
                g = fminf(g, LIMIT);
                u = fminf(fmaxf(u, -LIMIT), LIMIT);
                float glu = g / (1.0f + __expf(-ALPHA * g));
                g_actf[abase + j] = (u + 1.0f) * glu;
            }
        }
    }
}

// ---------------------------------------------------------------------------
// activation quantize: block per (expert, bucket row). absmax + int8 h/l.
// ---------------------------------------------------------------------------
__global__ __launch_bounds__(256) void quant_act_kernel() {
    int e = blockIdx.y, r = blockIdx.x, tid = threadIdx.x;
    if (r >= g_cnt[e]) return;
    size_t base = ((size_t)e * S + r) * INTER;
    const float4* src = (const float4*)(g_actf + base);
    float4 v0 = src[tid], v1 = src[tid + 256];
    float m = fmaxf(fmaxf(fmaxf(fabsf(v0.x), fabsf(v0.y)), fmaxf(fabsf(v0.z), fabsf(v0.w))),
                    fmaxf(fmaxf(fabsf(v1.x), fabsf(v1.y)), fmaxf(fabsf(v1.z), fabsf(v1.w))));
    __shared__ float sm[256];
    sm[tid] = m;
    __syncthreads();
    for (int s = 128; s > 0; s >>= 1) {
        if (tid < s) sm[tid] = fmaxf(sm[tid], sm[tid + s]);
        __syncthreads();
    }
    float amax = sm[0];
    float inv = amax > 0.0f ? 127.0f / amax : 0.0f;
    if (tid == 0) g_as[e * S + r] = amax / 127.0f;
    uint32_t* dh = (uint32_t*)(g_a8h + base);
    uint32_t* dl = (uint32_t*)(g_a8l + base);
#pragma unroll
    for (int p = 0; p < 2; p++) {
        float4 v = p ? v1 : v0;
        int h0, l0, h1, l1, h2, l2, h3, l3;
        quant2(v.x * inv, h0, l0); quant2(v.y * inv, h1, l1);
        quant2(v.z * inv, h2, l2); quant2(v.w * inv, h3, l3);
        dh[tid + p * 256] = (h0 & 0xFF) | ((h1 & 0xFF) << 8) | ((h2 & 0xFF) << 16) | ((h3 & 0xFF) << 24);
        dl[tid + p * 256] = (l0 & 0xFF) | ((l1 & 0xFF) << 8) | ((l2 & 0xFF) << 16) | ((l3 & 0xFF) << 24);
    }
}

// ---------------------------------------------------------------------------
// down int8 MMA: CTA = (expert, 128-row M-tile, 64-h N-tile). K = 2048 bytes,
// 16 chunks of 128. Epilogue: scales + bias + weighted atomicAdd.
// ---------------------------------------------------------------------------
__global__ __launch_bounds__(128, 2) void down_mma_kernel(
    const float* __restrict__ dbias, float* __restrict__ out)
{
    int e = blockIdx.z, mt = blockIdx.x, nt = blockIdx.y;
    int cnt = g_cnt[e];
    if (mt * 128 >= cnt) return;

    extern __shared__ char smem[];
    uint32_t T0 = (s2u(smem) + 1023) & ~1023u;
    int tid = threadIdx.x, wid = tid >> 5, lane = tid & 31;
    int wm = (wid >> 1) * 64, wn = (wid & 1) * 32;
    int h0 = nt * 64;

    int seg = tid & 7;
    size_t asrc[8], bsrc[4];
    uint32_t adst[8], bdst[4];
#pragma unroll
    for (int i = 0; i < 8; i++) {
        int row = (tid >> 3) + 16 * i;
        int tr = min(mt * 128 + row, cnt - 1);
        asrc[i] = ((size_t)e * S + tr) * INTER + seg * 16;
        adst[i] = swz128((uint32_t)(row * 128 + seg * 16));
    }
#pragma unroll
    for (int i = 0; i < 4; i++) {
        int row = (tid >> 3) + 16 * i;                 // 0..63
        bsrc[i] = ((size_t)e * H + h0 + row) * INTER + seg * 16;
        bdst[i] = swz128((uint32_t)(row * 128 + seg * 16));
    }

    int acc1[4][4][4], acc2[4][4][4];
#pragma unroll
    for (int a = 0; a < 4; a++)
#pragma unroll
        for (int b = 0; b < 4; b++)
#pragma unroll
            for (int c = 0; c < 4; c++) { acc1[a][b][c] = 0; acc2[a][b][c] = 0; }

    issue_chunk(T0, 0, g_a8h, g_a8l, g_dw8h, g_dw8l, asrc, bsrc, adst, bdst);
#pragma unroll 1
    for (int c = 0; c < 16; c++) {
        CP_WAIT0();
        __syncthreads();
        if (c + 1 < 16)
            issue_chunk(T0 + ((c + 1) & 1) * STAGE, (c + 1) * 128,
                        g_a8h, g_a8l, g_dw8h, g_dw8l, asrc, bsrc, adst, bdst);
        compute_chunk(T0 + (c & 1) * STAGE, wm, wn, lane, acc1, acc2);
    }

    const float* db = dbias + (size_t)e * H;
    const float* ds = g_dws + (size_t)e * H;
#pragma unroll
    for (int mf = 0; mf < 4; mf++) {
        int r0 = wm + mf * 16 + (lane >> 2);
#pragma unroll
        for (int half = 0; half < 2; half++) {
            int mrow = mt * 128 + r0 + half * 8;
            if (mrow >= cnt) continue;
            int tok = g_tok[e * S + mrow];
            float w = g_wt[e * S + mrow];
            float sa = g_as[e * S + mrow];
            float* orow = out + (size_t)tok * H;
#pragma unroll
            for (int nf = 0; nf < 4; nf++) {
                int h = h0 + wn + nf * 8 + 2 * (lane & 3);
                float v0 = (float)acc1[mf][nf][half * 2 + 0]
                         + (float)acc2[mf][nf][half * 2 + 0] * 0.0078125f;
                float v1 = (float)acc1[mf][nf][half * 2 + 1]
                         + (float)acc2[mf][nf][half * 2 + 1] * 0.0078125f;
                atomicAdd(orow + h,     w * (sa * ds[h] * v0 + db[h]));
                atomicAdd(orow + h + 1, w * (sa * ds[h + 1] * v1 + db[h + 1]));
            }
        }
    }
}

// ---------------------------------------------------------------------------
extern "C" void kernel_launch(void* const* d_in, const int* in_sizes, int n_in,
                              void* d_out, int out_size) {
    const float* x     = (const float*)d_in[0];
    const float* rw    = (const float*)d_in[1];
    const float* rb    = (const float*)d_in[2];
    const float* gup   = (const float*)d_in[3];
    const float* gub   = (const float*)d_in[4];
    const float* dwn   = (const float*)d_in[5];
    const float* dbias = (const float*)d_in[6];
    float* out = (float*)d_out;

    cudaFuncSetAttribute(gateup_mma_kernel, cudaFuncAttributeMaxDynamicSharedMemorySize, SMEM_REQ);
    cudaFuncSetAttribute(down_mma_kernel,   cudaFuncAttributeMaxDynamicSharedMemorySize, SMEM_REQ);

    cudaMemsetAsync(out, 0, (size_t)out_size * sizeof(float));
    init_kernel<<<1, 32>>>();
    router_kernel<<<S, 256>>>(x, rw, rb);
    quant_x_kernel<<<S, 256>>>(x);

    {   // weight absmax over original layouts
        dim3 g0(TWO_I / 32, E); absmax_w_kernel<0><<<g0, 256>>>(gup);
        dim3 g1(H / 32, E);     absmax_w_kernel<1><<<g1, 256>>>(dwn);
    }
    {   // gate_up weights: [E][1024][4096] -> [E][4096][1024] int8
        dim3 g(H / 64, TWO_I / 32, E);
        transpose_quant_kernel<0><<<g, 256>>>(gup);
    }
    {   // down weights: [E][2048][1024] -> [E][1024][2048] int8
        dim3 g(INTER / 64, H / 32, E);
        transpose_quant_kernel<1><<<g, 256>>>(dwn);
    }
    {
        dim3 g(S / 128, INTER / 32, E);   // (16, 64, 8), early-exit past bucket count
        gateup_mma_kernel<<<g, 128, SMEM_REQ>>>(gub);
    }
    {
        dim3 g(S, E);                     // block per (expert, row), early-exit
        quant_act_kernel<<<g, 256>>>();
    }
    {
        dim3 g(S / 128, H / 64, E);       // (16, 16, 8)
        down_mma_kernel<<<g, 128, SMEM_REQ>>>(dbias, out);
    }
}

// round 9
// speedup vs baseline: 3.2342x; 3.2342x over previous
#include <cuda_runtime.h>
#include <cuda_fp16.h>
#include <cstdint>

#define S 2048
#define H 1024
#define E 8
#define INTER 2048
#define TWO_I 4096
#define ALPHA 1.702f
#define LIMIT 7.0f

// ---------------- device scratch (device-code references ONLY) ----------------
__device__ int   g_cnt[E];
__device__ int   g_tok[E * S];
__device__ float g_wt[E * S];
// x split into fp16 digits (A-side of gate_up)
__device__ __align__(128) __half g_xh[S * H];
__device__ __align__(128) __half g_xl[S * H];
// gate_up weights transposed, single fp16: [E][N=4096][K=1024]
__device__ __align__(128) __half g_guh[(size_t)E * TWO_I * H];
// down weights transposed, single fp16: [E][N=H][K=INTER]
__device__ __align__(128) __half g_dwh[(size_t)E * H * INTER];
// activations split into fp16 digits (A-side of down)
__device__ __align__(128) __half g_ah[(size_t)E * S * INTER];
__device__ __align__(128) __half g_al[(size_t)E * S * INTER];

// ---------------- helpers ----------------
__device__ __forceinline__ uint32_t s2u(const void* p) {
    uint32_t a;
    asm("{ .reg .u64 t; cvta.to.shared.u64 t, %1; cvt.u32.u64 %0, t; }" : "=r"(a) : "l"(p));
    return a;
}
__device__ __forceinline__ uint32_t swz128(uint32_t o) { return o ^ ((o >> 3) & 0x70); }

#define CP16(dst, src) \
    asm volatile("cp.async.cg.shared.global [%0], [%1], 16;" :: "r"(dst), "l"(src) : "memory")
#define CP_COMMIT() asm volatile("cp.async.commit_group;" ::: "memory")
#define CP_WAIT0()  asm volatile("cp.async.wait_group 0;" ::: "memory")

__device__ __forceinline__ void ldsm4(uint32_t addr, uint32_t* r) {
    asm volatile("ldmatrix.sync.aligned.m8n8.x4.shared.b16 {%0,%1,%2,%3}, [%4];"
                 : "=r"(r[0]), "=r"(r[1]), "=r"(r[2]), "=r"(r[3]) : "r"(addr));
}
__device__ __forceinline__ void mma16816(float* d, const uint32_t* a, uint32_t b0, uint32_t b1) {
    asm volatile(
        "mma.sync.aligned.m16n8k16.row.col.f32.f16.f16.f32 "
        "{%0,%1,%2,%3}, {%4,%5,%6,%7}, {%8,%9}, {%0,%1,%2,%3};"
        : "+f"(d[0]), "+f"(d[1]), "+f"(d[2]), "+f"(d[3])
        : "r"(a[0]), "r"(a[1]), "r"(a[2]), "r"(a[3]), "r"(b0), "r"(b1));
}

// Stage: Ah 16K | Al 16K | Bh 8K = 40KB; 2 stages, 2 CTAs/SM
#define AOFF_L 16384
#define BOFF_H 32768
#define STAGE  40960
#define SMEM_REQ (1024 + 2 * STAGE)

// one K=64 chunk of 2-term split MMA; block tile 128x64, warp tile 64x32 (4 warps)
__device__ __forceinline__ void compute_chunk(uint32_t base, int wm, int wn, int lane,
                                              float acc[4][4][4])
{
    uint32_t sA = base, sAl = base + AOFF_L, sB = base + BOFF_H;
    int arow = wm + (lane & 15);
    int brow = wn + (lane & 15);
    uint32_t klane = (uint32_t)((lane >> 4) << 4);
#pragma unroll
    for (int ks = 0; ks < 4; ks++) {
        uint32_t ko = (uint32_t)(ks * 32) + klane;
        uint32_t ah[4][4], al[4][4];
#pragma unroll
        for (int mf = 0; mf < 4; mf++) {
            uint32_t off = swz128((uint32_t)((arow + mf * 16) * 128) + ko);
            ldsm4(sA + off, ah[mf]);
            ldsm4(sAl + off, al[mf]);
        }
#pragma unroll
        for (int nh = 0; nh < 2; nh++) {
            uint32_t boff = swz128((uint32_t)((brow + nh * 16) * 128) + ko);
            uint32_t bh[4];
            ldsm4(sB + boff, bh);
#pragma unroll
            for (int mf = 0; mf < 4; mf++) {
                mma16816(acc[mf][2 * nh],     ah[mf], bh[0], bh[2]);
                mma16816(acc[mf][2 * nh],     al[mf], bh[0], bh[2]);
                mma16816(acc[mf][2 * nh + 1], ah[mf], bh[1], bh[3]);
                mma16816(acc[mf][2 * nh + 1], al[mf], bh[1], bh[3]);
            }
        }
    }
}

// 128 threads: A rows 0..127 (8 CP16 per array), B rows 0..63 (4 CP16)
__device__ __forceinline__ void issue_chunk(
    uint32_t base, int k0,
    const __half* Ah, const __half* Al, const __half* Bh,
    const size_t* asrc, const size_t* bsrc,
    const uint32_t* adst, const uint32_t* bdst)
{
#pragma unroll
    for (int i = 0; i < 8; i++) {
        CP16(base +          adst[i], (const char*)(Ah + asrc[i] + k0));
        CP16(base + AOFF_L + adst[i], (const char*)(Al + asrc[i] + k0));
    }
#pragma unroll
    for (int i = 0; i < 4; i++)
        CP16(base + BOFF_H + bdst[i], (const char*)(Bh + bsrc[i] + k0));
    CP_COMMIT();
}

// ---------------------------------------------------------------------------
__global__ void init_kernel() {
    if (threadIdx.x < E) g_cnt[threadIdx.x] = 0;
}

// ---------------------------------------------------------------------------
__global__ __launch_bounds__(256) void router_kernel(
    const float* __restrict__ x, const float* __restrict__ rw, const float* __restrict__ rb)
{
    int t = blockIdx.x;
    int tid = threadIdx.x;
    const float* xr = x + (size_t)t * H;

    float acc[E];
#pragma unroll
    for (int e = 0; e < E; e++) acc[e] = 0.0f;
    for (int h = tid; h < H; h += 256) {
        float xv = xr[h];
        const float4* wrow = (const float4*)(rw + (size_t)h * E);
        float4 w0 = wrow[0], w1 = wrow[1];
        acc[0] += xv * w0.x; acc[1] += xv * w0.y; acc[2] += xv * w0.z; acc[3] += xv * w0.w;
        acc[4] += xv * w1.x; acc[5] += xv * w1.y; acc[6] += xv * w1.z; acc[7] += xv * w1.w;
    }
    __shared__ float sm[256 * E];
#pragma unroll
    for (int e = 0; e < E; e++) sm[tid * E + e] = acc[e];
    __syncthreads();
    for (int s = 128; s > 0; s >>= 1) {
        if (tid < s) {
#pragma unroll
            for (int e = 0; e < E; e++) sm[tid * E + e] += sm[(tid + s) * E + e];
        }
        __syncthreads();
    }
    if (tid == 0) {
        float v[E];
#pragma unroll
        for (int e = 0; e < E; e++) v[e] = sm[e] + rb[e];
        int i0 = 0;
#pragma unroll
        for (int e = 1; e < E; e++) if (v[e] > v[i0]) i0 = e;
        int i1 = -1;
#pragma unroll
        for (int e = 0; e < E; e++) {
            if (e == i0) continue;
            if (i1 < 0 || v[e] > v[i1]) i1 = e;
        }
        float e1 = expf(v[i1] - v[i0]);
        float den = 1.0f + e1;
        int p0 = atomicAdd(&g_cnt[i0], 1);
        g_tok[i0 * S + p0] = t; g_wt[i0 * S + p0] = 1.0f / den;
        int p1 = atomicAdd(&g_cnt[i1], 1);
        g_tok[i1 * S + p1] = t; g_wt[i1 * S + p1] = e1 / den;
    }
}

// ---------------------------------------------------------------------------
// x -> fp16 hi/lo digits
// ---------------------------------------------------------------------------
__global__ __launch_bounds__(256) void conv_x_kernel(const float* __restrict__ x) {
    int i = blockIdx.x * 256 + threadIdx.x;           // 4 elements each
    float4 v = ((const float4*)x)[i];
    __half h0 = __float2half(v.x), h1 = __float2half(v.y);
    __half h2 = __float2half(v.z), h3 = __float2half(v.w);
    __half l0 = __float2half(v.x - __half2float(h0));
    __half l1 = __float2half(v.y - __half2float(h1));
    __half l2 = __float2half(v.z - __half2float(h2));
    __half l3 = __float2half(v.w - __half2float(h3));
    ((__half2*)g_xh)[2 * i]     = __halves2half2(h0, h1);
    ((__half2*)g_xh)[2 * i + 1] = __halves2half2(h2, h3);
    ((__half2*)g_xl)[2 * i]     = __halves2half2(l0, l1);
    ((__half2*)g_xl)[2 * i + 1] = __halves2half2(l2, l3);
}

// ---------------------------------------------------------------------------
// weight transpose to single fp16, outputs bound in DEVICE code.
// in [E][R][C] fp32 -> out [E][C][R] fp16. Tile 64(R) x 32(C).
// ---------------------------------------------------------------------------
template <int WHICH>   // 0 = gate_up (R=H, C=2I), 1 = down (R=INTER, C=H)
__global__ __launch_bounds__(256) void transpose_half_kernel(const float* __restrict__ in)
{
    const int R = (WHICH == 0) ? H : INTER;
    const int C = (WHICH == 0) ? TWO_I : H;
    __half* ohi = (WHICH == 0) ? g_guh : g_dwh;

    int e = blockIdx.z;
    int r0 = blockIdx.x * 64;
    int c0 = blockIdx.y * 32;
    __shared__ float t[64][33];
    int tx = threadIdx.x & 31, ty = threadIdx.x >> 5;
    const float* ib = in + ((size_t)e * R + r0) * C + c0;
#pragma unroll
    for (int i = 0; i < 8; i++)
        t[ty + 8 * i][tx] = ib[(size_t)(ty + 8 * i) * C + tx];
    __syncthreads();
#pragma unroll
    for (int i = 0; i < 4; i++) {
        int c = ty + 8 * i;
        float a = t[2 * tx][c], b = t[2 * tx + 1][c];
        size_t o = ((size_t)e * C + c0 + c) * R + r0 + 2 * tx;
        *(__half2*)(ohi + o) = __halves2half2(__float2half(a), __float2half(b));
    }
}

// ---------------------------------------------------------------------------
// gate_up: CTA = (expert, 128-token M-tile, 32-j N-tile = 64 interleaved cols).
// 128 threads, 4 warps of 64x32. K = H = 1024, 16 chunks of 64.
// ---------------------------------------------------------------------------
__global__ __launch_bounds__(128, 2) void gateup_mma_kernel(const float* __restrict__ gub) {
    int e = blockIdx.z, mt = blockIdx.x, nt = blockIdx.y;
    int cnt = g_cnt[e];
    if (mt * 128 >= cnt) return;

    extern __shared__ char smem[];
    uint32_t T0 = (s2u(smem) + 1023) & ~1023u;
    int tid = threadIdx.x, wid = tid >> 5, lane = tid & 31;
    int wm = (wid >> 1) * 64, wn = (wid & 1) * 32;
    int j0 = nt * 32;

    int seg = tid & 7;
    size_t asrc[8], bsrc[4];
    uint32_t adst[8], bdst[4];
#pragma unroll
    for (int i = 0; i < 8; i++) {
        int row = (tid >> 3) + 16 * i;                 // 0..127
        int tr = min(mt * 128 + row, cnt - 1);
        int tok = g_tok[e * S + tr];
        asrc[i] = (size_t)tok * H + seg * 8;
        adst[i] = swz128((uint32_t)(row * 128 + seg * 16));
    }
#pragma unroll
    for (int i = 0; i < 4; i++) {
        int row = (tid >> 3) + 16 * i;                 // 0..63
        int br = (row & 1) ? (INTER + j0 + (row >> 1)) : (j0 + (row >> 1));
        bsrc[i] = ((size_t)e * TWO_I + br) * H + seg * 8;
        bdst[i] = swz128((uint32_t)(row * 128 + seg * 16));
    }

    float acc[4][4][4];
#pragma unroll
    for (int a = 0; a < 4; a++)
#pragma unroll
        for (int b = 0; b < 4; b++)
#pragma unroll
            for (int c = 0; c < 4; c++) acc[a][b][c] = 0.0f;

    issue_chunk(T0, 0, g_xh, g_xl, g_guh, asrc, bsrc, adst, bdst);
#pragma unroll 1
    for (int c = 0; c < 16; c++) {
        CP_WAIT0();
        __syncthreads();
        if (c + 1 < 16)
            issue_chunk(T0 + ((c + 1) & 1) * STAGE, (c + 1) * 64,
                        g_xh, g_xl, g_guh, asrc, bsrc, adst, bdst);
        compute_chunk(T0 + (c & 1) * STAGE, wm, wn, lane, acc);
    }

    const float* gb = gub + (size_t)e * TWO_I;
#pragma unroll
    for (int mf = 0; mf < 4; mf++) {
        int r0 = wm + mf * 16 + (lane >> 2);
#pragma unroll
        for (int half = 0; half < 2; half++) {
            int mrow = mt * 128 + r0 + half * 8;
            if (mrow >= cnt) continue;
            size_t abase = ((size_t)e * S + mrow) * INTER;
#pragma unroll
            for (int nf = 0; nf < 4; nf++) {
                int nn = wn + nf * 8 + 2 * (lane & 3);
                int j = j0 + (nn >> 1);
                float g = acc[mf][nf][half * 2 + 0] + gb[j];
                float u = acc[mf][nf][half * 2 + 1] + gb[INTER + j];
                g = fminf(g, LIMIT);
                u = fminf(fmaxf(u, -LIMIT), LIMIT);
                float glu = g / (1.0f + __expf(-ALPHA * g));
                float av = (u + 1.0f) * glu;
                __half hi = __float2half(av);
                __half lo = __float2half(av - __half2float(hi));
                g_ah[abase + j] = hi;
                g_al[abase + j] = lo;
            }
        }
    }
}

// ---------------------------------------------------------------------------
// down: CTA = (expert, 128-row M-tile, 64-h N-tile). 128 threads, 4 warps.
// K = INTER = 2048, 32 chunks of 64.
// ---------------------------------------------------------------------------
__global__ __launch_bounds__(128, 2) void down_mma_kernel(
    const float* __restrict__ dbias, float* __restrict__ out)
{
    int e = blockIdx.z, mt = blockIdx.x, nt = blockIdx.y;
    int cnt = g_cnt[e];
    if (mt * 128 >= cnt) return;

    extern __shared__ char smem[];
    uint32_t T0 = (s2u(smem) + 1023) & ~1023u;
    int tid = threadIdx.x, wid = tid >> 5, lane = tid & 31;
    int wm = (wid >> 1) * 64, wn = (wid & 1) * 32;
    int h0 = nt * 64;

    int seg = tid & 7;
    size_t asrc[8], bsrc[4];
    uint32_t adst[8], bdst[4];
#pragma unroll
    for (int i = 0; i < 8; i++) {
        int row = (tid >> 3) + 16 * i;
        int tr = min(mt * 128 + row, cnt - 1);
        asrc[i] = ((size_t)e * S + tr) * INTER + seg * 8;
        adst[i] = swz128((uint32_t)(row * 128 + seg * 16));
    }
#pragma unroll
    for (int i = 0; i < 4; i++) {
        int row = (tid >> 3) + 16 * i;                 // 0..63
        bsrc[i] = ((size_t)e * H + h0 + row) * INTER + seg * 8;
        bdst[i] = swz128((uint32_t)(row * 128 + seg * 16));
    }

    float acc[4][4][4];
#pragma unroll
    for (int a = 0; a < 4; a++)
#pragma unroll
        for (int b = 0; b < 4; b++)
#pragma unroll
            for (int c = 0; c < 4; c++) acc[a][b][c] = 0.0f;

    issue_chunk(T0, 0, g_ah, g_al, g_dwh, asrc, bsrc, adst, bdst);
#pragma unroll 1
    for (int c = 0; c < 32; c++) {
        CP_WAIT0();
        __syncthreads();
        if (c + 1 < 32)
            issue_chunk(T0 + ((c + 1) & 1) * STAGE, (c + 1) * 64,
                        g_ah, g_al, g_dwh, asrc, bsrc, adst, bdst);
        compute_chunk(T0 + (c & 1) * STAGE, wm, wn, lane, acc);
    }

    const float* db = dbias + (size_t)e * H;
#pragma unroll
    for (int mf = 0; mf < 4; mf++) {
        int r0 = wm + mf * 16 + (lane >> 2);
#pragma unroll
        for (int half = 0; half < 2; half++) {
            int mrow = mt * 128 + r0 + half * 8;
            if (mrow >= cnt) continue;
            int tok = g_tok[e * S + mrow];
            float w = g_wt[e * S + mrow];
            float* orow = out + (size_t)tok * H;
#pragma unroll
            for (int nf = 0; nf < 4; nf++) {
                int h = h0 + wn + nf * 8 + 2 * (lane & 3);
                float v0 = acc[mf][nf][half * 2 + 0] + db[h];
                float v1 = acc[mf][nf][half * 2 + 1] + db[h + 1];
                atomicAdd(orow + h,     w * v0);
                atomicAdd(orow + h + 1, w * v1);
            }
        }
    }
}

// ---------------------------------------------------------------------------
extern "C" void kernel_launch(void* const* d_in, const int* in_sizes, int n_in,
                              void* d_out, int out_size) {
    const float* x     = (const float*)d_in[0];
    const float* rw    = (const float*)d_in[1];
    const float* rb    = (const float*)d_in[2];
    const float* gup   = (const float*)d_in[3];
    const float* gub   = (const float*)d_in[4];
    const float* dwn   = (const float*)d_in[5];
    const float* dbias = (const float*)d_in[6];
    float* out = (float*)d_out;

    cudaFuncSetAttribute(gateup_mma_kernel, cudaFuncAttributeMaxDynamicSharedMemorySize, SMEM_REQ);
    cudaFuncSetAttribute(down_mma_kernel,   cudaFuncAttributeMaxDynamicSharedMemorySize, SMEM_REQ);

    cudaMemsetAsync(out, 0, (size_t)out_size * sizeof(float));
    init_kernel<<<1, 32>>>();
    router_kernel<<<S, 256>>>(x, rw, rb);
    conv_x_kernel<<<(S * H / 4) / 256, 256>>>(x);

    {   // gate_up weights: [E][1024][4096] -> [E][4096][1024] fp16
        dim3 g(H / 64, TWO_I / 32, E);
        transpose_half_kernel<0><<<g, 256>>>(gup);
    }
    {   // down weights: [E][2048][1024] -> [E][1024][2048] fp16
        dim3 g(INTER / 64, H / 32, E);
        transpose_half_kernel<1><<<g, 256>>>(dwn);
    }
    {
        dim3 g(S / 128, INTER / 32, E);   // (16, 64, 8), early-exit past bucket count
        gateup_mma_kernel<<<g, 128, SMEM_REQ>>>(gub);
    }
    {
        dim3 g(S / 128, H / 64, E);       // (16, 16, 8)
        down_mma_kernel<<<g, 128, SMEM_REQ>>>(dbias, out);
    }
}

// round 10
// speedup vs baseline: 4.9256x; 1.5230x over previous
#include <cuda_runtime.h>
#include <cuda_fp16.h>
#include <cstdint>

#define S 2048
#define H 1024
#define E 8
#define INTER 2048
#define TWO_I 4096
#define ALPHA 1.702f
#define LIMIT 7.0f

// ---------------- device scratch (device-code references ONLY) ----------------
__device__ int   g_cnt[E];
__device__ int   g_tok[E * S];
__device__ float g_wt[E * S];
// x in fp16 (A-side of gate_up)
__device__ __align__(128) __half g_xh[S * H];
// gate_up weights transposed fp16: [E][N=4096][K=1024]
__device__ __align__(128) __half g_guh[(size_t)E * TWO_I * H];
// down weights transposed fp16: [E][N=H][K=INTER]
__device__ __align__(128) __half g_dwh[(size_t)E * H * INTER];
// activations fp16 (A-side of down)
__device__ __align__(128) __half g_ah[(size_t)E * S * INTER];

// ---------------- helpers ----------------
__device__ __forceinline__ uint32_t s2u(const void* p) {
    uint32_t a;
    asm("{ .reg .u64 t; cvta.to.shared.u64 t, %1; cvt.u32.u64 %0, t; }" : "=r"(a) : "l"(p));
    return a;
}
__device__ __forceinline__ uint32_t swz128(uint32_t o) { return o ^ ((o >> 3) & 0x70); }

#define CP16(dst, src) \
    asm volatile("cp.async.cg.shared.global [%0], [%1], 16;" :: "r"(dst), "l"(src) : "memory")
#define CP_COMMIT() asm volatile("cp.async.commit_group;" ::: "memory")
#define CP_WAIT0()  asm volatile("cp.async.wait_group 0;" ::: "memory")

__device__ __forceinline__ void ldsm4(uint32_t addr, uint32_t* r) {
    asm volatile("ldmatrix.sync.aligned.m8n8.x4.shared.b16 {%0,%1,%2,%3}, [%4];"
                 : "=r"(r[0]), "=r"(r[1]), "=r"(r[2]), "=r"(r[3]) : "r"(addr));
}
__device__ __forceinline__ void mma16816(float* d, const uint32_t* a, uint32_t b0, uint32_t b1) {
    asm volatile(
        "mma.sync.aligned.m16n8k16.row.col.f32.f16.f16.f32 "
        "{%0,%1,%2,%3}, {%4,%5,%6,%7}, {%8,%9}, {%0,%1,%2,%3};"
        : "+f"(d[0]), "+f"(d[1]), "+f"(d[2]), "+f"(d[3])
        : "r"(a[0]), "r"(a[1]), "r"(a[2]), "r"(a[3]), "r"(b0), "r"(b1));
}

// Stage: Ah 16K | Bh 8K = 24KB; 2 stages -> ~4 CTAs/SM
#define BOFF_H 16384
#define STAGE  24576
#define SMEM_REQ (1024 + 2 * STAGE)

// one K=64 chunk; block tile 128x64, warp tile 64x32 (4 warps), single fp16 term
__device__ __forceinline__ void compute_chunk(uint32_t base, int wm, int wn, int lane,
                                              float acc[4][4][4])
{
    uint32_t sA = base, sB = base + BOFF_H;
    int arow = wm + (lane & 15);
    int brow = wn + (lane & 15);
    uint32_t klane = (uint32_t)((lane >> 4) << 4);
#pragma unroll
    for (int ks = 0; ks < 4; ks++) {
        uint32_t ko = (uint32_t)(ks * 32) + klane;
        uint32_t ah[4][4];
#pragma unroll
        for (int mf = 0; mf < 4; mf++) {
            uint32_t off = swz128((uint32_t)((arow + mf * 16) * 128) + ko);
            ldsm4(sA + off, ah[mf]);
        }
#pragma unroll
        for (int nh = 0; nh < 2; nh++) {
            uint32_t boff = swz128((uint32_t)((brow + nh * 16) * 128) + ko);
            uint32_t bh[4];
            ldsm4(sB + boff, bh);
#pragma unroll
            for (int mf = 0; mf < 4; mf++) {
                mma16816(acc[mf][2 * nh],     ah[mf], bh[0], bh[2]);
                mma16816(acc[mf][2 * nh + 1], ah[mf], bh[1], bh[3]);
            }
        }
    }
}

// 128 threads: A rows 0..127 (8 CP16), B rows 0..63 (4 CP16)
__device__ __forceinline__ void issue_chunk(
    uint32_t base, int k0,
    const __half* Ah, const __half* Bh,
    const size_t* asrc, const size_t* bsrc,
    const uint32_t* adst, const uint32_t* bdst)
{
#pragma unroll
    for (int i = 0; i < 8; i++)
        CP16(base + adst[i], (const char*)(Ah + asrc[i] + k0));
#pragma unroll
    for (int i = 0; i < 4; i++)
        CP16(base + BOFF_H + bdst[i], (const char*)(Bh + bsrc[i] + k0));
    CP_COMMIT();
}

// ---------------------------------------------------------------------------
__global__ void init_kernel() {
    if (threadIdx.x < E) g_cnt[threadIdx.x] = 0;
}

// ---------------------------------------------------------------------------
__global__ __launch_bounds__(256) void router_kernel(
    const float* __restrict__ x, const float* __restrict__ rw, const float* __restrict__ rb)
{
    int t = blockIdx.x;
    int tid = threadIdx.x;
    const float* xr = x + (size_t)t * H;

    float acc[E];
#pragma unroll
    for (int e = 0; e < E; e++) acc[e] = 0.0f;
    for (int h = tid; h < H; h += 256) {
        float xv = xr[h];
        const float4* wrow = (const float4*)(rw + (size_t)h * E);
        float4 w0 = wrow[0], w1 = wrow[1];
        acc[0] += xv * w0.x; acc[1] += xv * w0.y; acc[2] += xv * w0.z; acc[3] += xv * w0.w;
        acc[4] += xv * w1.x; acc[5] += xv * w1.y; acc[6] += xv * w1.z; acc[7] += xv * w1.w;
    }
    __shared__ float sm[256 * E];
#pragma unroll
    for (int e = 0; e < E; e++) sm[tid * E + e] = acc[e];
    __syncthreads();
    for (int s = 128; s > 0; s >>= 1) {
        if (tid < s) {
#pragma unroll
            for (int e = 0; e < E; e++) sm[tid * E + e] += sm[(tid + s) * E + e];
        }
        __syncthreads();
    }
    if (tid == 0) {
        float v[E];
#pragma unroll
        for (int e = 0; e < E; e++) v[e] = sm[e] + rb[e];
        int i0 = 0;
#pragma unroll
        for (int e = 1; e < E; e++) if (v[e] > v[i0]) i0 = e;
        int i1 = -1;
#pragma unroll
        for (int e = 0; e < E; e++) {
            if (e == i0) continue;
            if (i1 < 0 || v[e] > v[i1]) i1 = e;
        }
        float e1 = expf(v[i1] - v[i0]);
        float den = 1.0f + e1;
        int p0 = atomicAdd(&g_cnt[i0], 1);
        g_tok[i0 * S + p0] = t; g_wt[i0 * S + p0] = 1.0f / den;
        int p1 = atomicAdd(&g_cnt[i1], 1);
        g_tok[i1 * S + p1] = t; g_wt[i1 * S + p1] = e1 / den;
    }
}

// ---------------------------------------------------------------------------
__global__ __launch_bounds__(256) void conv_x_kernel(const float* __restrict__ x) {
    int i = blockIdx.x * 256 + threadIdx.x;           // 4 elements each
    float4 v = ((const float4*)x)[i];
    ((__half2*)g_xh)[2 * i]     = __halves2half2(__float2half(v.x), __float2half(v.y));
    ((__half2*)g_xh)[2 * i + 1] = __halves2half2(__float2half(v.z), __float2half(v.w));
}

// ---------------------------------------------------------------------------
// weight transpose to fp16, outputs bound in DEVICE code.
// in [E][R][C] fp32 -> out [E][C][R] fp16. Tile 64(R) x 32(C).
// ---------------------------------------------------------------------------
template <int WHICH>   // 0 = gate_up (R=H, C=2I), 1 = down (R=INTER, C=H)
__global__ __launch_bounds__(256) void transpose_half_kernel(const float* __restrict__ in)
{
    const int R = (WHICH == 0) ? H : INTER;
    const int C = (WHICH == 0) ? TWO_I : H;
    __half* ohi = (WHICH == 0) ? g_guh : g_dwh;

    int e = blockIdx.z;
    int r0 = blockIdx.x * 64;
    int c0 = blockIdx.y * 32;
    __shared__ float t[64][33];
    int tx = threadIdx.x & 31, ty = threadIdx.x >> 5;
    const float* ib = in + ((size_t)e * R + r0) * C + c0;
#pragma unroll
    for (int i = 0; i < 8; i++)
        t[ty + 8 * i][tx] = ib[(size_t)(ty + 8 * i) * C + tx];
    __syncthreads();
#pragma unroll
    for (int i = 0; i < 4; i++) {
        int c = ty + 8 * i;
        float a = t[2 * tx][c], b = t[2 * tx + 1][c];
        size_t o = ((size_t)e * C + c0 + c) * R + r0 + 2 * tx;
        *(__half2*)(ohi + o) = __halves2half2(__float2half(a), __float2half(b));
    }
}

// ---------------------------------------------------------------------------
// gate_up: CTA = (expert, 128-token M-tile, 32-j N-tile = 64 interleaved cols).
// 128 threads, 4 warps of 64x32. K = H = 1024, 16 chunks of 64.
// ---------------------------------------------------------------------------
__global__ __launch_bounds__(128, 4) void gateup_mma_kernel(const float* __restrict__ gub) {
    int e = blockIdx.z, mt = blockIdx.x, nt = blockIdx.y;
    int cnt = g_cnt[e];
    if (mt * 128 >= cnt) return;

    extern __shared__ char smem[];
    uint32_t T0 = (s2u(smem) + 1023) & ~1023u;
    int tid = threadIdx.x, wid = tid >> 5, lane = tid & 31;
    int wm = (wid >> 1) * 64, wn = (wid & 1) * 32;
    int j0 = nt * 32;

    int seg = tid & 7;
    size_t asrc[8], bsrc[4];
    uint32_t adst[8], bdst[4];
#pragma unroll
    for (int i = 0; i < 8; i++) {
        int row = (tid >> 3) + 16 * i;                 // 0..127
        int tr = min(mt * 128 + row, cnt - 1);
        int tok = g_tok[e * S + tr];
        asrc[i] = (size_t)tok * H + seg * 8;
        adst[i] = swz128((uint32_t)(row * 128 + seg * 16));
    }
#pragma unroll
    for (int i = 0; i < 4; i++) {
        int row = (tid >> 3) + 16 * i;                 // 0..63
        int br = (row & 1) ? (INTER + j0 + (row >> 1)) : (j0 + (row >> 1));
        bsrc[i] = ((size_t)e * TWO_I + br) * H + seg * 8;
        bdst[i] = swz128((uint32_t)(row * 128 + seg * 16));
    }

    float acc[4][4][4];
#pragma unroll
    for (int a = 0; a < 4; a++)
#pragma unroll
        for (int b = 0; b < 4; b++)
#pragma unroll
            for (int c = 0; c < 4; c++) acc[a][b][c] = 0.0f;

    issue_chunk(T0, 0, g_xh, g_guh, asrc, bsrc, adst, bdst);
#pragma unroll 1
    for (int c = 0; c < 16; c++) {
        CP_WAIT0();
        __syncthreads();
        if (c + 1 < 16)
            issue_chunk(T0 + ((c + 1) & 1) * STAGE, (c + 1) * 64,
                        g_xh, g_guh, asrc, bsrc, adst, bdst);
        compute_chunk(T0 + (c & 1) * STAGE, wm, wn, lane, acc);
    }

    const float* gb = gub + (size_t)e * TWO_I;
#pragma unroll
    for (int mf = 0; mf < 4; mf++) {
        int r0 = wm + mf * 16 + (lane >> 2);
#pragma unroll
        for (int half = 0; half < 2; half++) {
            int mrow = mt * 128 + r0 + half * 8;
            if (mrow >= cnt) continue;
            size_t abase = ((size_t)e * S + mrow) * INTER;
#pragma unroll
            for (int nf = 0; nf < 4; nf++) {
                int nn = wn + nf * 8 + 2 * (lane & 3);
                int j = j0 + (nn >> 1);
                float g = acc[mf][nf][half * 2 + 0] + gb[j];
                float u = acc[mf][nf][half * 2 + 1] + gb[INTER + j];
                g = fminf(g, LIMIT);
                u = fminf(fmaxf(u, -LIMIT), LIMIT);
                float glu = g / (1.0f + __expf(-ALPHA * g));
                g_ah[abase + j] = __float2half((u + 1.0f) * glu);
            }
        }
    }
}

// ---------------------------------------------------------------------------
// down: CTA = (expert, 128-row M-tile, 64-h N-tile). 128 threads, 4 warps.
// K = INTER = 2048, 32 chunks of 64.
// ---------------------------------------------------------------------------
__global__ __launch_bounds__(128, 4) void down_mma_kernel(
    const float* __restrict__ dbias, float* __restrict__ out)
{
    int e = blockIdx.z, mt = blockIdx.x, nt = blockIdx.y;
    int cnt = g_cnt[e];
    if (mt * 128 >= cnt) return;

    extern __shared__ char smem[];
    uint32_t T0 = (s2u(smem) + 1023) & ~1023u;
    int tid = threadIdx.x, wid = tid >> 5, lane = tid & 31;
    int wm = (wid >> 1) * 64, wn = (wid & 1) * 32;
    int h0 = nt * 64;

    int seg = tid & 7;
    size_t asrc[8], bsrc[4];
    uint32_t adst[8], bdst[4];
#pragma unroll
    for (int i = 0; i < 8; i++) {
        int row = (tid >> 3) + 16 * i;
        int tr = min(mt * 128 + row, cnt - 1);
        asrc[i] = ((size_t)e * S + tr) * INTER + seg * 8;
        adst[i] = swz128((uint32_t)(row * 128 + seg * 16));
    }
#pragma unroll
    for (int i = 0; i < 4; i++) {
        int row = (tid >> 3) + 16 * i;                 // 0..63
        bsrc[i] = ((size_t)e * H + h0 + row) * INTER + seg * 8;
        bdst[i] = swz128((uint32_t)(row * 128 + seg * 16));
    }

    float acc[4][4][4];
#pragma unroll
    for (int a = 0; a < 4; a++)
#pragma unroll
        for (int b = 0; b < 4; b++)
#pragma unroll
            for (int c = 0; c < 4; c++) acc[a][b][c] = 0.0f;

    issue_chunk(T0, 0, g_ah, g_dwh, asrc, bsrc, adst, bdst);
#pragma unroll 1
    for (int c = 0; c < 32; c++) {
        CP_WAIT0();
        __syncthreads();
        if (c + 1 < 32)
            issue_chunk(T0 + ((c + 1) & 1) * STAGE, (c + 1) * 64,
                        g_ah, g_dwh, asrc, bsrc, adst, bdst);
        compute_chunk(T0 + (c & 1) * STAGE, wm, wn, lane, acc);
    }

    const float* db = dbias + (size_t)e * H;
#pragma unroll
    for (int mf = 0; mf < 4; mf++) {
        int r0 = wm + mf * 16 + (lane >> 2);
#pragma unroll
        for (int half = 0; half < 2; half++) {
            int mrow = mt * 128 + r0 + half * 8;
            if (mrow >= cnt) continue;
            int tok = g_tok[e * S + mrow];
            float w = g_wt[e * S + mrow];
            float* orow = out + (size_t)tok * H;
#pragma unroll
            for (int nf = 0; nf < 4; nf++) {
                int h = h0 + wn + nf * 8 + 2 * (lane & 3);
                float v0 = acc[mf][nf][half * 2 + 0] + db[h];
                float v1 = acc[mf][nf][half * 2 + 1] + db[h + 1];
                atomicAdd(orow + h,     w * v0);
                atomicAdd(orow + h + 1, w * v1);
            }
        }
    }
}

// ---------------------------------------------------------------------------
extern "C" void kernel_launch(void* const* d_in, const int* in_sizes, int n_in,
                              void* d_out, int out_size) {
    const float* x     = (const float*)d_in[0];
    const float* rw    = (const float*)d_in[1];
    const float* rb    = (const float*)d_in[2];
    const float* gup   = (const float*)d_in[3];
    const float* gub   = (const float*)d_in[4];
    const float* dwn   = (const float*)d_in[5];
    const float* dbias = (const float*)d_in[6];
    float* out = (float*)d_out;

    cudaFuncSetAttribute(gateup_mma_kernel, cudaFuncAttributeMaxDynamicSharedMemorySize, SMEM_REQ);
    cudaFuncSetAttribute(down_mma_kernel,   cudaFuncAttributeMaxDynamicSharedMemorySize, SMEM_REQ);

    cudaMemsetAsync(out, 0, (size_t)out_size * sizeof(float));
    init_kernel<<<1, 32>>>();
    router_kernel<<<S, 256>>>(x, rw, rb);
    conv_x_kernel<<<(S * H / 4) / 256, 256>>>(x);

    {   // gate_up weights: [E][1024][4096] -> [E][4096][1024] fp16
        dim3 g(H / 64, TWO_I / 32, E);
        transpose_half_kernel<0><<<g, 256>>>(gup);
    }
    {   // down weights: [E][2048][1024] -> [E][1024][2048] fp16
        dim3 g(INTER / 64, H / 32, E);
        transpose_half_kernel<1><<<g, 256>>>(dwn);
    }
    {
        dim3 g(S / 128, INTER / 32, E);   // (16, 64, 8), early-exit past bucket count
        gateup_mma_kernel<<<g, 128, SMEM_REQ>>>(gub);
    }
    {
        dim3 g(S / 128, H / 64, E);       // (16, 16, 8)
        down_mma_kernel<<<g, 128, SMEM_REQ>>>(dbias, out);
    }
}

// round 11
// speedup vs baseline: 5.4103x; 1.0984x over previous
#include <cuda_runtime.h>
#include <cuda_fp16.h>
#include <cstdint>

#define S 2048
#define H 1024
#define E 8
#define INTER 2048
#define TWO_I 4096
#define ALPHA 1.702f
#define LIMIT 7.0f

// ---------------- device scratch (device-code references ONLY) ----------------
__device__ int   g_cnt[E];
__device__ int   g_tok[E * S];
__device__ float g_wt[E * S];
__device__ __align__(128) __half g_xh[S * H];
__device__ __align__(128) __half g_guh[(size_t)E * TWO_I * H];
__device__ __align__(128) __half g_dwh[(size_t)E * H * INTER];
__device__ __align__(128) __half g_ah[(size_t)E * S * INTER];

// ---------------- helpers ----------------
__device__ __forceinline__ uint32_t s2u(const void* p) {
    uint32_t a;
    asm("{ .reg .u64 t; cvta.to.shared.u64 t, %1; cvt.u32.u64 %0, t; }" : "=r"(a) : "l"(p));
    return a;
}
__device__ __forceinline__ uint32_t swz128(uint32_t o) { return o ^ ((o >> 3) & 0x70); }

#define CP16(dst, src) \
    asm volatile("cp.async.cg.shared.global [%0], [%1], 16;" :: "r"(dst), "l"(src) : "memory")
#define CP_COMMIT() asm volatile("cp.async.commit_group;" ::: "memory")
#define CP_WAIT0()  asm volatile("cp.async.wait_group 0;" ::: "memory")
#define CP_WAIT1()  asm volatile("cp.async.wait_group 1;" ::: "memory")

__device__ __forceinline__ void ldsm4(uint32_t addr, uint32_t* r) {
    asm volatile("ldmatrix.sync.aligned.m8n8.x4.shared.b16 {%0,%1,%2,%3}, [%4];"
                 : "=r"(r[0]), "=r"(r[1]), "=r"(r[2]), "=r"(r[3]) : "r"(addr));
}
__device__ __forceinline__ void mma16816(float* d, const uint32_t* a, uint32_t b0, uint32_t b1) {
    asm volatile(
        "mma.sync.aligned.m16n8k16.row.col.f32.f16.f16.f32 "
        "{%0,%1,%2,%3}, {%4,%5,%6,%7}, {%8,%9}, {%0,%1,%2,%3};"
        : "+f"(d[0]), "+f"(d[1]), "+f"(d[2]), "+f"(d[3])
        : "r"(a[0]), "r"(a[1]), "r"(a[2]), "r"(a[3]), "r"(b0), "r"(b1));
}

// Stage: Ah 16K | Bh 8K = 24KB; 3 stages -> 3 CTAs/SM
#define BOFF_H 16384
#define STAGE  24576
#define SMEM_REQ (1024 + 3 * STAGE)

// one K=64 chunk; block tile 128x64, warp tile 64x32 (4 warps), single fp16 term
__device__ __forceinline__ void compute_chunk(uint32_t base, int wm, int wn, int lane,
                                              float acc[4][4][4])
{
    uint32_t sA = base, sB = base + BOFF_H;
    int arow = wm + (lane & 15);
    int brow = wn + (lane & 15);
    uint32_t klane = (uint32_t)((lane >> 4) << 4);
#pragma unroll
    for (int ks = 0; ks < 4; ks++) {
        uint32_t ko = (uint32_t)(ks * 32) + klane;
        uint32_t ah[4][4];
#pragma unroll
        for (int mf = 0; mf < 4; mf++) {
            uint32_t off = swz128((uint32_t)((arow + mf * 16) * 128) + ko);
            ldsm4(sA + off, ah[mf]);
        }
#pragma unroll
        for (int nh = 0; nh < 2; nh++) {
            uint32_t boff = swz128((uint32_t)((brow + nh * 16) * 128) + ko);
            uint32_t bh[4];
            ldsm4(sB + boff, bh);
#pragma unroll
            for (int mf = 0; mf < 4; mf++) {
                mma16816(acc[mf][2 * nh],     ah[mf], bh[0], bh[2]);
                mma16816(acc[mf][2 * nh + 1], ah[mf], bh[1], bh[3]);
            }
        }
    }
}

// 128 threads: A rows 0..127 (8 CP16), B rows 0..63 (4 CP16)
__device__ __forceinline__ void issue_chunk(
    uint32_t base, int k0,
    const __half* Ah, const __half* Bh,
    const size_t* asrc, const size_t* bsrc,
    const uint32_t* adst, const uint32_t* bdst)
{
#pragma unroll
    for (int i = 0; i < 8; i++)
        CP16(base + adst[i], (const char*)(Ah + asrc[i] + k0));
#pragma unroll
    for (int i = 0; i < 4; i++)
        CP16(base + BOFF_H + bdst[i], (const char*)(Bh + bsrc[i] + k0));
    CP_COMMIT();
}

// ---------------------------------------------------------------------------
__global__ void init_kernel() {
    if (threadIdx.x < E) g_cnt[threadIdx.x] = 0;
}

// ---------------------------------------------------------------------------
// Router: one warp per token, shuffle reduce. 8 tokens per 256-thread block.
// ---------------------------------------------------------------------------
__global__ __launch_bounds__(256) void router_kernel(
    const float* __restrict__ x, const float* __restrict__ rw, const float* __restrict__ rb)
{
    int warp = threadIdx.x >> 5, lane = threadIdx.x & 31;
    int t = blockIdx.x * 8 + warp;
    const float* xr = x + (size_t)t * H;

    float acc[E];
#pragma unroll
    for (int e = 0; e < E; e++) acc[e] = 0.0f;
#pragma unroll 4
    for (int i = 0; i < 32; i++) {
        int h = i * 32 + lane;
        float xv = xr[h];
        const float4* wrow = (const float4*)(rw + (size_t)h * E);
        float4 w0 = wrow[0], w1 = wrow[1];
        acc[0] += xv * w0.x; acc[1] += xv * w0.y; acc[2] += xv * w0.z; acc[3] += xv * w0.w;
        acc[4] += xv * w1.x; acc[5] += xv * w1.y; acc[6] += xv * w1.z; acc[7] += xv * w1.w;
    }
#pragma unroll
    for (int off = 16; off > 0; off >>= 1)
#pragma unroll
        for (int e = 0; e < E; e++)
            acc[e] += __shfl_down_sync(0xffffffffu, acc[e], off);

    if (lane == 0) {
        float v[E];
#pragma unroll
        for (int e = 0; e < E; e++) v[e] = acc[e] + rb[e];
        int i0 = 0;
#pragma unroll
        for (int e = 1; e < E; e++) if (v[e] > v[i0]) i0 = e;
        int i1 = -1;
#pragma unroll
        for (int e = 0; e < E; e++) {
            if (e == i0) continue;
            if (i1 < 0 || v[e] > v[i1]) i1 = e;
        }
        float e1 = expf(v[i1] - v[i0]);
        float den = 1.0f + e1;
        int p0 = atomicAdd(&g_cnt[i0], 1);
        g_tok[i0 * S + p0] = t; g_wt[i0 * S + p0] = 1.0f / den;
        int p1 = atomicAdd(&g_cnt[i1], 1);
        g_tok[i1 * S + p1] = t; g_wt[i1 * S + p1] = e1 / den;
    }
}

// ---------------------------------------------------------------------------
__global__ __launch_bounds__(256) void conv_x_kernel(const float* __restrict__ x) {
    int i = blockIdx.x * 256 + threadIdx.x;           // 4 elements each
    float4 v = ((const float4*)x)[i];
    ((__half2*)g_xh)[2 * i]     = __halves2half2(__float2half(v.x), __float2half(v.y));
    ((__half2*)g_xh)[2 * i + 1] = __halves2half2(__float2half(v.z), __float2half(v.w));
}

// ---------------------------------------------------------------------------
// weight transpose to fp16, outputs bound in DEVICE code.
// in [E][R][C] fp32 -> out [E][C][R] fp16. Tile 64(R) x 32(C).
// ---------------------------------------------------------------------------
template <int WHICH>   // 0 = gate_up (R=H, C=2I), 1 = down (R=INTER, C=H)
__global__ __launch_bounds__(256) void transpose_half_kernel(const float* __restrict__ in)
{
    const int R = (WHICH == 0) ? H : INTER;
    const int C = (WHICH == 0) ? TWO_I : H;
    __half* ohi = (WHICH == 0) ? g_guh : g_dwh;

    int e = blockIdx.z;
    int r0 = blockIdx.x * 64;
    int c0 = blockIdx.y * 32;
    __shared__ float t[64][33];
    int tx = threadIdx.x & 31, ty = threadIdx.x >> 5;
    const float* ib = in + ((size_t)e * R + r0) * C + c0;
#pragma unroll
    for (int i = 0; i < 8; i++)
        t[ty + 8 * i][tx] = ib[(size_t)(ty + 8 * i) * C + tx];
    __syncthreads();
#pragma unroll
    for (int i = 0; i < 4; i++) {
        int c = ty + 8 * i;
        float a = t[2 * tx][c], b = t[2 * tx + 1][c];
        size_t o = ((size_t)e * C + c0 + c) * R + r0 + 2 * tx;
        *(__half2*)(ohi + o) = __halves2half2(__float2half(a), __float2half(b));
    }
}

// ---------------------------------------------------------------------------
// gate_up: CTA = (expert, 128-token M-tile, 32-j N-tile = 64 interleaved cols).
// 128 threads, 4 warps of 64x32. K = H = 1024, 16 chunks of 64.
// 3-stage cp.async pipeline.
// ---------------------------------------------------------------------------
__global__ __launch_bounds__(128, 3) void gateup_mma_kernel(const float* __restrict__ gub) {
    int e = blockIdx.z, mt = blockIdx.x, nt = blockIdx.y;
    int cnt = g_cnt[e];
    if (mt * 128 >= cnt) return;

    extern __shared__ char smem[];
    uint32_t T0 = (s2u(smem) + 1023) & ~1023u;
    int tid = threadIdx.x, wid = tid >> 5, lane = tid & 31;
    int wm = (wid >> 1) * 64, wn = (wid & 1) * 32;
    int j0 = nt * 32;

    int seg = tid & 7;
    size_t asrc[8], bsrc[4];
    uint32_t adst[8], bdst[4];
#pragma unroll
    for (int i = 0; i < 8; i++) {
        int row = (tid >> 3) + 16 * i;                 // 0..127
        int tr = min(mt * 128 + row, cnt - 1);
        int tok = g_tok[e * S + tr];
        asrc[i] = (size_t)tok * H + seg * 8;
        adst[i] = swz128((uint32_t)(row * 128 + seg * 16));
    }
#pragma unroll
    for (int i = 0; i < 4; i++) {
        int row = (tid >> 3) + 16 * i;                 // 0..63
        int br = (row & 1) ? (INTER + j0 + (row >> 1)) : (j0 + (row >> 1));
        bsrc[i] = ((size_t)e * TWO_I + br) * H + seg * 8;
        bdst[i] = swz128((uint32_t)(row * 128 + seg * 16));
    }

    float acc[4][4][4];
#pragma unroll
    for (int a = 0; a < 4; a++)
#pragma unroll
        for (int b = 0; b < 4; b++)
#pragma unroll
            for (int c = 0; c < 4; c++) acc[a][b][c] = 0.0f;

    issue_chunk(T0,         0,  g_xh, g_guh, asrc, bsrc, adst, bdst);
    issue_chunk(T0 + STAGE, 64, g_xh, g_guh, asrc, bsrc, adst, bdst);
    int stage = 0;
#pragma unroll 1
    for (int c = 0; c < 16; c++) {
        if (c + 1 < 16) { CP_WAIT1(); } else { CP_WAIT0(); }
        __syncthreads();
        if (c + 2 < 16) {
            int s2 = stage + 2; if (s2 >= 3) s2 -= 3;
            issue_chunk(T0 + s2 * STAGE, (c + 2) * 64, g_xh, g_guh, asrc, bsrc, adst, bdst);
        }
        compute_chunk(T0 + stage * STAGE, wm, wn, lane, acc);
        stage = (stage + 1 == 3) ? 0 : stage + 1;
    }

    const float* gb = gub + (size_t)e * TWO_I;
#pragma unroll
    for (int mf = 0; mf < 4; mf++) {
        int r0 = wm + mf * 16 + (lane >> 2);
#pragma unroll
        for (int half = 0; half < 2; half++) {
            int mrow = mt * 128 + r0 + half * 8;
            if (mrow >= cnt) continue;
            size_t abase = ((size_t)e * S + mrow) * INTER;
#pragma unroll
            for (int nf = 0; nf < 4; nf++) {
                int nn = wn + nf * 8 + 2 * (lane & 3);
                int j = j0 + (nn >> 1);
                float g = acc[mf][nf][half * 2 + 0] + gb[j];
                float u = acc[mf][nf][half * 2 + 1] + gb[INTER + j];
                g = fminf(g, LIMIT);
                u = fminf(fmaxf(u, -LIMIT), LIMIT);
                float glu = g / (1.0f + __expf(-ALPHA * g));
                g_ah[abase + j] = __float2half((u + 1.0f) * glu);
            }
        }
    }
}

// ---------------------------------------------------------------------------
// down: CTA = (expert, 128-row M-tile, 64-h N-tile). 128 threads, 4 warps.
// K = INTER = 2048, 32 chunks of 64. 3-stage pipeline.
// ---------------------------------------------------------------------------
__global__ __launch_bounds__(128, 3) void down_mma_kernel(
    const float* __restrict__ dbias, float* __restrict__ out)
{
    int e = blockIdx.z, mt = blockIdx.x, nt = blockIdx.y;
    int cnt = g_cnt[e];
    if (mt * 128 >= cnt) return;

    extern __shared__ char smem[];
    uint32_t T0 = (s2u(smem) + 1023) & ~1023u;
    int tid = threadIdx.x, wid = tid >> 5, lane = tid & 31;
    int wm = (wid >> 1) * 64, wn = (wid & 1) * 32;
    int h0 = nt * 64;

    int seg = tid & 7;
    size_t asrc[8], bsrc[4];
    uint32_t adst[8], bdst[4];
#pragma unroll
    for (int i = 0; i < 8; i++) {
        int row = (tid >> 3) + 16 * i;
        int tr = min(mt * 128 + row, cnt - 1);
        asrc[i] = ((size_t)e * S + tr) * INTER + seg * 8;
        adst[i] = swz128((uint32_t)(row * 128 + seg * 16));
    }
#pragma unroll
    for (int i = 0; i < 4; i++) {
        int row = (tid >> 3) + 16 * i;                 // 0..63
        bsrc[i] = ((size_t)e * H + h0 + row) * INTER + seg * 8;
        bdst[i] = swz128((uint32_t)(row * 128 + seg * 16));
    }

    float acc[4][4][4];
#pragma unroll
    for (int a = 0; a < 4; a++)
#pragma unroll
        for (int b = 0; b < 4; b++)
#pragma unroll
            for (int c = 0; c < 4; c++) acc[a][b][c] = 0.0f;

    issue_chunk(T0,         0,  g_ah, g_dwh, asrc, bsrc, adst, bdst);
    issue_chunk(T0 + STAGE, 64, g_ah, g_dwh, asrc, bsrc, adst, bdst);
    int stage = 0;
#pragma unroll 1
    for (int c = 0; c < 32; c++) {
        if (c + 1 < 32) { CP_WAIT1(); } else { CP_WAIT0(); }
        __syncthreads();
        if (c + 2 < 32) {
            int s2 = stage + 2; if (s2 >= 3) s2 -= 3;
            issue_chunk(T0 + s2 * STAGE, (c + 2) * 64, g_ah, g_dwh, asrc, bsrc, adst, bdst);
        }
        compute_chunk(T0 + stage * STAGE, wm, wn, lane, acc);
        stage = (stage + 1 == 3) ? 0 : stage + 1;
    }

    const float* db = dbias + (size_t)e * H;
#pragma unroll
    for (int mf = 0; mf < 4; mf++) {
        int r0 = wm + mf * 16 + (lane >> 2);
#pragma unroll
        for (int half = 0; half < 2; half++) {
            int mrow = mt * 128 + r0 + half * 8;
            if (mrow >= cnt) continue;
            int tok = g_tok[e * S + mrow];
            float w = g_wt[e * S + mrow];
            float* orow = out + (size_t)tok * H;
#pragma unroll
            for (int nf = 0; nf < 4; nf++) {
                int h = h0 + wn + nf * 8 + 2 * (lane & 3);
                float v0 = acc[mf][nf][half * 2 + 0] + db[h];
                float v1 = acc[mf][nf][half * 2 + 1] + db[h + 1];
                atomicAdd(orow + h,     w * v0);
                atomicAdd(orow + h + 1, w * v1);
            }
        }
    }
}

// ---------------------------------------------------------------------------
extern "C" void kernel_launch(void* const* d_in, const int* in_sizes, int n_in,
                              void* d_out, int out_size) {
    const float* x     = (const float*)d_in[0];
    const float* rw    = (const float*)d_in[1];
    const float* rb    = (const float*)d_in[2];
    const float* gup   = (const float*)d_in[3];
    const float* gub   = (const float*)d_in[4];
    const float* dwn   = (const float*)d_in[5];
    const float* dbias = (const float*)d_in[6];
    float* out = (float*)d_out;

    cudaFuncSetAttribute(gateup_mma_kernel, cudaFuncAttributeMaxDynamicSharedMemorySize, SMEM_REQ);
    cudaFuncSetAttribute(down_mma_kernel,   cudaFuncAttributeMaxDynamicSharedMemorySize, SMEM_REQ);

    cudaMemsetAsync(out, 0, (size_t)out_size * sizeof(float));
    init_kernel<<<1, 32>>>();
    router_kernel<<<S / 8, 256>>>(x, rw, rb);
    conv_x_kernel<<<(S * H / 4) / 256, 256>>>(x);

    {   // gate_up weights: [E][1024][4096] -> [E][4096][1024] fp16
        dim3 g(H / 64, TWO_I / 32, E);
        transpose_half_kernel<0><<<g, 256>>>(gup);
    }
    {   // down weights: [E][2048][1024] -> [E][1024][2048] fp16
        dim3 g(INTER / 64, H / 32, E);
        transpose_half_kernel<1><<<g, 256>>>(dwn);
    }
    {
        dim3 g(S / 128, INTER / 32, E);   // (16, 64, 8), early-exit past bucket count
        gateup_mma_kernel<<<g, 128, SMEM_REQ>>>(gub);
    }
    {
        dim3 g(S / 128, H / 64, E);       // (16, 16, 8)
        down_mma_kernel<<<g, 128, SMEM_REQ>>>(dbias, out);
    }
}